// round 5
// baseline (speedup 1.0000x reference)
#include <cuda_runtime.h>
#include <cstdint>

#define NNODES 5000000
#define NGRAPHS 100000
#define NODES_PER_GRAPH 50

// L2-resident scratch (20 MB each, 80 MB total).
__device__ int   g_deg[NNODES];
__device__ float g_dis[NNODES];
__device__ float g_p[NNODES];    // xw[i] * dis[i]
__device__ float g_acc[NNODES];  // running scatter sum (init = p[i] == self-loop term)
__device__ int   g_is64;         // 1 if edge_index is int64, 0 if int32

// ---------------------------------------------------------------------------
// 1) init degree to 1 (self loop) + dtype detect (thread 0 of block 0).
//    int64 indices < 2^31 have all-zero high 32-bit words.
__global__ void k_init(const unsigned long long* __restrict__ e)
{
    long long i = (long long)blockIdx.x * blockDim.x + threadIdx.x;
    if (i < NNODES) g_deg[i] = 1;
    if (i == 0) {
        int is64 = 1;
#pragma unroll
        for (int k = 0; k < 8; ++k)
            if ((e[k] >> 32) != 0ull) is64 = 0;
        g_is64 = is64;
    }
}

// ---------------------------------------------------------------------------
// 2) degree count: RED.ADD to g_deg[col]. 16 edges/thread, streaming index loads.
__global__ void k_count(const long long* __restrict__ col64,
                        const int* __restrict__ col32, long long E)
{
    long long t    = (long long)blockIdx.x * blockDim.x + threadIdx.x;
    long long base = t * 16;
    if (g_is64) {
        if (base + 15 < E) {
#pragma unroll
            for (int k = 0; k < 8; ++k) {
                longlong2 a = __ldcs(reinterpret_cast<const longlong2*>(col64 + base + 2 * k));
                atomicAdd(&g_deg[(int)a.x], 1);
                atomicAdd(&g_deg[(int)a.y], 1);
            }
        } else {
            for (long long j = base; j < E; ++j)
                atomicAdd(&g_deg[(int)__ldcs(col64 + j)], 1);
        }
    } else {
        if (base + 15 < E) {
#pragma unroll
            for (int k = 0; k < 4; ++k) {
                int4 c = __ldcs(reinterpret_cast<const int4*>(col32 + base + 4 * k));
                atomicAdd(&g_deg[c.x], 1);
                atomicAdd(&g_deg[c.y], 1);
                atomicAdd(&g_deg[c.z], 1);
                atomicAdd(&g_deg[c.w], 1);
            }
        } else {
            for (long long j = base; j < E; ++j)
                atomicAdd(&g_deg[__ldcs(col32 + j)], 1);
        }
    }
}

// ---------------------------------------------------------------------------
// 3) per-node prep: dis = rsqrt(deg); p = x*w*dis; acc starts at p (self loop)
__global__ void k_prep(const float* __restrict__ x,
                       const float* __restrict__ conv_w)
{
    int i = blockIdx.x * blockDim.x + threadIdx.x;
    if (i < NNODES) {
        float dis = rsqrtf((float)g_deg[i]);
        float p   = x[i] * conv_w[0] * dis;
        g_dis[i] = dis;
        g_p[i]   = p;
        g_acc[i] = p;
    }
}

// ---------------------------------------------------------------------------
// 4) edge scatter: acc[col] += p[row]. One 4B gather + one 4B RED per edge.
//    16 edges/thread: batch index loads, then gathers (deep MLP), then REDs.
__global__ void k_edge(const long long* __restrict__ row64,
                       const long long* __restrict__ col64,
                       const int* __restrict__ row32,
                       const int* __restrict__ col32, long long E)
{
    long long t    = (long long)blockIdx.x * blockDim.x + threadIdx.x;
    long long base = t * 16;
    int r[16], c[16];
    if (g_is64) {
        if (base + 15 < E) {
#pragma unroll
            for (int k = 0; k < 8; ++k) {
                longlong2 rr = __ldcs(reinterpret_cast<const longlong2*>(row64 + base + 2 * k));
                longlong2 cc = __ldcs(reinterpret_cast<const longlong2*>(col64 + base + 2 * k));
                r[2 * k]     = (int)rr.x;
                r[2 * k + 1] = (int)rr.y;
                c[2 * k]     = (int)cc.x;
                c[2 * k + 1] = (int)cc.y;
            }
            float p[16];
#pragma unroll
            for (int k = 0; k < 16; ++k) p[k] = __ldg(&g_p[r[k]]);
#pragma unroll
            for (int k = 0; k < 16; ++k) atomicAdd(&g_acc[c[k]], p[k]);
        } else {
            for (long long j = base; j < E; ++j)
                atomicAdd(&g_acc[(int)__ldcs(col64 + j)],
                          __ldg(&g_p[(int)__ldcs(row64 + j)]));
        }
    } else {
        if (base + 15 < E) {
#pragma unroll
            for (int k = 0; k < 4; ++k) {
                int4 rr = __ldcs(reinterpret_cast<const int4*>(row32 + base + 4 * k));
                int4 cc = __ldcs(reinterpret_cast<const int4*>(col32 + base + 4 * k));
                r[4 * k] = rr.x; r[4 * k + 1] = rr.y; r[4 * k + 2] = rr.z; r[4 * k + 3] = rr.w;
                c[4 * k] = cc.x; c[4 * k + 1] = cc.y; c[4 * k + 2] = cc.z; c[4 * k + 3] = cc.w;
            }
            float p[16];
#pragma unroll
            for (int k = 0; k < 16; ++k) p[k] = __ldg(&g_p[r[k]]);
#pragma unroll
            for (int k = 0; k < 16; ++k) atomicAdd(&g_acc[c[k]], p[k]);
        } else {
            for (long long j = base; j < E; ++j)
                atomicAdd(&g_acc[__ldcs(col32 + j)], __ldg(&g_p[__ldcs(row32 + j)]));
        }
    }
}

// ---------------------------------------------------------------------------
// 5) fused h = dis*acc + conv_b  and per-graph FC (50 -> 2).
__global__ void k_fc(const float* __restrict__ conv_b,
                     const float* __restrict__ fc_w,   // [2,50] row-major
                     const float* __restrict__ fc_b,   // [2]
                     float* __restrict__ out)          // [NGRAPHS,2]
{
    int g = blockIdx.x * blockDim.x + threadIdx.x;
    if (g >= NGRAPHS) return;
    float b  = conv_b[0];
    float s0 = fc_b[0];
    float s1 = fc_b[1];
    int base = g * NODES_PER_GRAPH;
#pragma unroll
    for (int j = 0; j < NODES_PER_GRAPH; ++j) {
        float h = g_dis[base + j] * g_acc[base + j] + b;
        s0 = fmaf(h, __ldg(&fc_w[j]), s0);
        s1 = fmaf(h, __ldg(&fc_w[NODES_PER_GRAPH + j]), s1);
    }
    out[2 * g]     = s0;
    out[2 * g + 1] = s1;
}

// ---------------------------------------------------------------------------
extern "C" void kernel_launch(void* const* d_in, const int* in_sizes, int n_in,
                              void* d_out, int out_size)
{
    // Resolve inputs BY SIZE. Sizes: x=5,000,000; edge_index=160,000,000
    // (elements, dtype int32 or int64 — detected on device);
    // conv_w=1; conv_b=1 (in appearance order); fc_w=100; fc_b=2.
    const float* x      = nullptr;
    const void*  eidx   = nullptr;
    const float* conv_w = nullptr;
    const float* conv_b = nullptr;
    const float* fc_w   = nullptr;
    const float* fc_b   = nullptr;
    long long    n_edge_elems = 0;

    for (int i = 0; i < n_in; ++i) {
        long long s = in_sizes[i];
        if (s == 160000000LL)      { eidx = d_in[i]; n_edge_elems = s; }
        else if (s == 5000000LL)   { x    = (const float*)d_in[i]; }
        else if (s == 100LL)       { fc_w = (const float*)d_in[i]; }
        else if (s == 2LL)         { fc_b = (const float*)d_in[i]; }
        else if (s == 1LL) {
            if (!conv_w) conv_w = (const float*)d_in[i];
            else         conv_b = (const float*)d_in[i];
        }
    }

    float* out = (float*)d_out;
    const long long E = n_edge_elems / 2;

    const long long* row64 = (const long long*)eidx;
    const long long* col64 = row64 + E;
    const int*       row32 = (const int*)eidx;
    const int*       col32 = row32 + E;

    const int TPB  = 512;
    const int EPT  = 16;  // edges per thread
    int node_blocks = (NNODES + TPB - 1) / TPB;
    int edge_blocks = (int)((E + (long long)TPB * EPT - 1) / ((long long)TPB * EPT));
    int fc_blocks   = (NGRAPHS + TPB - 1) / TPB;

    // Launch order chosen so the ncu profiled slot (4th kernel) is k_edge.
    k_init <<<node_blocks, TPB>>>((const unsigned long long*)eidx);
    k_count<<<edge_blocks, TPB>>>(col64, col32, E);
    k_prep <<<node_blocks, TPB>>>(x, conv_w);
    k_edge <<<edge_blocks, TPB>>>(row64, col64, row32, col32, E);
    k_fc   <<<fc_blocks,   TPB>>>(conv_b, fc_w, fc_b, out);
}

// round 6
// speedup vs baseline: 1.5547x; 1.5547x over previous
#include <cuda_runtime.h>
#include <cstdint>

#define NNODES 5000000
#define NGRAPHS 100000
#define NODES_PER_GRAPH 50

// L2-resident scratch (20 MB each, 80 MB total).
__device__ int   g_deg[NNODES];
__device__ float g_dis[NNODES];
__device__ float g_p[NNODES];    // xw[i] * dis[i]
__device__ float g_acc[NNODES];  // running scatter sum (init = p[i] == self-loop term)
__device__ int   g_is64;         // 1 if edge_index is int64, 0 if int32

// ---------------------------------------------------------------------------
// 1) init degree to 1 (self loop), int4-vectorized; thread 0 also detects the
//    index dtype (int64 indices < 2^31 have all-zero high 32-bit words).
__global__ void k_init(const unsigned long long* __restrict__ e)
{
    int i = blockIdx.x * blockDim.x + threadIdx.x;          // int4 slot
    const int n4 = NNODES / 4;                               // 1,250,000
    if (i < n4)
        reinterpret_cast<int4*>(g_deg)[i] = make_int4(1, 1, 1, 1);
    if (i == 0) {
        int is64 = 1;
#pragma unroll
        for (int k = 0; k < 8; ++k)
            if ((e[k] >> 32) != 0ull) is64 = 0;
        g_is64 = is64;
    }
}

// ---------------------------------------------------------------------------
// 2) degree count: RED.ADD to g_deg[col]. 4 edges/thread.
__global__ void __launch_bounds__(256, 8)
k_count(const long long* __restrict__ col64,
        const int* __restrict__ col32, long long E)
{
    long long t    = (long long)blockIdx.x * blockDim.x + threadIdx.x;
    long long base = t * 4;
    if (g_is64) {
        if (base + 3 < E) {
            longlong2 a = *reinterpret_cast<const longlong2*>(col64 + base);
            longlong2 b = *reinterpret_cast<const longlong2*>(col64 + base + 2);
            atomicAdd(&g_deg[(int)a.x], 1);
            atomicAdd(&g_deg[(int)a.y], 1);
            atomicAdd(&g_deg[(int)b.x], 1);
            atomicAdd(&g_deg[(int)b.y], 1);
        } else {
            for (long long j = base; j < E; ++j)
                atomicAdd(&g_deg[(int)col64[j]], 1);
        }
    } else {
        if (base + 3 < E) {
            int4 c = *reinterpret_cast<const int4*>(col32 + base);
            atomicAdd(&g_deg[c.x], 1);
            atomicAdd(&g_deg[c.y], 1);
            atomicAdd(&g_deg[c.z], 1);
            atomicAdd(&g_deg[c.w], 1);
        } else {
            for (long long j = base; j < E; ++j)
                atomicAdd(&g_deg[col32[j]], 1);
        }
    }
}

// ---------------------------------------------------------------------------
// 3) per-node prep: dis = rsqrt(deg); p = x*w*dis; acc starts at p (self loop)
__global__ void k_prep(const float* __restrict__ x,
                       const float* __restrict__ conv_w)
{
    int i = blockIdx.x * blockDim.x + threadIdx.x;
    if (i < NNODES) {
        float dis = rsqrtf((float)g_deg[i]);
        float p   = x[i] * conv_w[0] * dis;
        g_dis[i] = dis;
        g_p[i]   = p;
        g_acc[i] = p;
    }
}

// ---------------------------------------------------------------------------
// 4) edge scatter: acc[col] += p[row]. One 4B gather + one 4B RED per edge.
//    4 edges/thread, gathers issued first (MLP), REDs fire-and-forget.
__global__ void __launch_bounds__(256, 8)
k_edge(const long long* __restrict__ row64,
       const long long* __restrict__ col64,
       const int* __restrict__ row32,
       const int* __restrict__ col32, long long E)
{
    long long t    = (long long)blockIdx.x * blockDim.x + threadIdx.x;
    long long base = t * 4;
    if (g_is64) {
        if (base + 3 < E) {
            longlong2 r0 = *reinterpret_cast<const longlong2*>(row64 + base);
            longlong2 r1 = *reinterpret_cast<const longlong2*>(row64 + base + 2);
            longlong2 c0 = *reinterpret_cast<const longlong2*>(col64 + base);
            longlong2 c1 = *reinterpret_cast<const longlong2*>(col64 + base + 2);
            float p0 = __ldg(&g_p[(int)r0.x]);
            float p1 = __ldg(&g_p[(int)r0.y]);
            float p2 = __ldg(&g_p[(int)r1.x]);
            float p3 = __ldg(&g_p[(int)r1.y]);
            atomicAdd(&g_acc[(int)c0.x], p0);
            atomicAdd(&g_acc[(int)c0.y], p1);
            atomicAdd(&g_acc[(int)c1.x], p2);
            atomicAdd(&g_acc[(int)c1.y], p3);
        } else {
            for (long long j = base; j < E; ++j)
                atomicAdd(&g_acc[(int)col64[j]], __ldg(&g_p[(int)row64[j]]));
        }
    } else {
        if (base + 3 < E) {
            int4 r = *reinterpret_cast<const int4*>(row32 + base);
            int4 c = *reinterpret_cast<const int4*>(col32 + base);
            float p0 = __ldg(&g_p[r.x]);
            float p1 = __ldg(&g_p[r.y]);
            float p2 = __ldg(&g_p[r.z]);
            float p3 = __ldg(&g_p[r.w]);
            atomicAdd(&g_acc[c.x], p0);
            atomicAdd(&g_acc[c.y], p1);
            atomicAdd(&g_acc[c.z], p2);
            atomicAdd(&g_acc[c.w], p3);
        } else {
            for (long long j = base; j < E; ++j)
                atomicAdd(&g_acc[col32[j]], __ldg(&g_p[row32[j]]));
        }
    }
}

// ---------------------------------------------------------------------------
// 5) fused h = dis*acc + conv_b  and per-graph FC (50 -> 2).
__global__ void k_fc(const float* __restrict__ conv_b,
                     const float* __restrict__ fc_w,   // [2,50] row-major
                     const float* __restrict__ fc_b,   // [2]
                     float* __restrict__ out)          // [NGRAPHS,2]
{
    int g = blockIdx.x * blockDim.x + threadIdx.x;
    if (g >= NGRAPHS) return;
    float b  = conv_b[0];
    float s0 = fc_b[0];
    float s1 = fc_b[1];
    int base = g * NODES_PER_GRAPH;
#pragma unroll
    for (int j = 0; j < NODES_PER_GRAPH; ++j) {
        float h = g_dis[base + j] * g_acc[base + j] + b;
        s0 = fmaf(h, __ldg(&fc_w[j]), s0);
        s1 = fmaf(h, __ldg(&fc_w[NODES_PER_GRAPH + j]), s1);
    }
    out[2 * g]     = s0;
    out[2 * g + 1] = s1;
}

// ---------------------------------------------------------------------------
extern "C" void kernel_launch(void* const* d_in, const int* in_sizes, int n_in,
                              void* d_out, int out_size)
{
    // Resolve inputs BY SIZE. Sizes: x=5,000,000; edge_index=160,000,000
    // (elements, dtype int32 or int64 — detected on device);
    // conv_w=1; conv_b=1 (in appearance order); fc_w=100; fc_b=2.
    const float* x      = nullptr;
    const void*  eidx   = nullptr;
    const float* conv_w = nullptr;
    const float* conv_b = nullptr;
    const float* fc_w   = nullptr;
    const float* fc_b   = nullptr;
    long long    n_edge_elems = 0;

    for (int i = 0; i < n_in; ++i) {
        long long s = in_sizes[i];
        if (s == 160000000LL)      { eidx = d_in[i]; n_edge_elems = s; }
        else if (s == 5000000LL)   { x    = (const float*)d_in[i]; }
        else if (s == 100LL)       { fc_w = (const float*)d_in[i]; }
        else if (s == 2LL)         { fc_b = (const float*)d_in[i]; }
        else if (s == 1LL) {
            if (!conv_w) conv_w = (const float*)d_in[i];
            else         conv_b = (const float*)d_in[i];
        }
    }

    float* out = (float*)d_out;
    const long long E = n_edge_elems / 2;

    const long long* row64 = (const long long*)eidx;
    const long long* col64 = row64 + E;
    const int*       row32 = (const int*)eidx;
    const int*       col32 = row32 + E;

    const int TPB = 256;
    int init_blocks = (NNODES / 4 + TPB - 1) / TPB;
    int node_blocks = (NNODES + TPB - 1) / TPB;
    int edge_blocks = (int)((E + (long long)TPB * 4 - 1) / ((long long)TPB * 4));
    int fc_blocks   = (NGRAPHS + TPB - 1) / TPB;

    k_init <<<init_blocks, TPB>>>((const unsigned long long*)eidx);
    k_count<<<edge_blocks, TPB>>>(col64, col32, E);
    k_prep <<<node_blocks, TPB>>>(x, conv_w);
    k_edge <<<edge_blocks, TPB>>>(row64, col64, row32, col32, E);
    k_fc   <<<fc_blocks,   TPB>>>(conv_b, fc_w, fc_b, out);
}

// round 7
// speedup vs baseline: 1.5811x; 1.0170x over previous
#include <cuda_runtime.h>
#include <cstdint>

#define NNODES 5000000
#define NGRAPHS 100000
#define NODES_PER_GRAPH 50

// L2-resident scratch (60 MB total).
__device__ int   g_deg[NNODES];  // edge count (self loop added as +1 at use sites)
__device__ float g_p[NNODES];    // xw[i] * dis[i]
__device__ float g_acc[NNODES];  // running scatter sum (init = p[i] == self-loop term)
__device__ int   g_is64;         // 1 if edge_index is int64, 0 if int32

// ---------------------------------------------------------------------------
// 0) dtype detect: int64 indices < 2^31 have all-zero high 32-bit words.
__global__ void k_detect(const unsigned long long* __restrict__ e)
{
    int is64 = 1;
#pragma unroll
    for (int k = 0; k < 8; ++k)
        if ((e[k] >> 32) != 0ull) is64 = 0;
    g_is64 = is64;
}

// ---------------------------------------------------------------------------
// 1) degree count: RED.ADD to g_deg[col]. 4 edges/thread. (At L2-slice floor.)
__global__ void __launch_bounds__(256, 8)
k_count(const long long* __restrict__ col64,
        const int* __restrict__ col32, long long E)
{
    long long t    = (long long)blockIdx.x * blockDim.x + threadIdx.x;
    long long base = t * 4;
    if (g_is64) {
        if (base + 3 < E) {
            longlong2 a = *reinterpret_cast<const longlong2*>(col64 + base);
            longlong2 b = *reinterpret_cast<const longlong2*>(col64 + base + 2);
            atomicAdd(&g_deg[(int)a.x], 1);
            atomicAdd(&g_deg[(int)a.y], 1);
            atomicAdd(&g_deg[(int)b.x], 1);
            atomicAdd(&g_deg[(int)b.y], 1);
        } else {
            for (long long j = base; j < E; ++j)
                atomicAdd(&g_deg[(int)col64[j]], 1);
        }
    } else {
        if (base + 3 < E) {
            int4 c = *reinterpret_cast<const int4*>(col32 + base);
            atomicAdd(&g_deg[c.x], 1);
            atomicAdd(&g_deg[c.y], 1);
            atomicAdd(&g_deg[c.z], 1);
            atomicAdd(&g_deg[c.w], 1);
        } else {
            for (long long j = base; j < E; ++j)
                atomicAdd(&g_deg[col32[j]], 1);
        }
    }
}

// ---------------------------------------------------------------------------
// 2) per-node prep, 4 nodes/thread vectorized:
//    dis = rsqrt(deg+1); p = x*w*dis; acc starts at p (self-loop term).
__global__ void k_prep(const float* __restrict__ x,
                       const float* __restrict__ conv_w)
{
    int i = blockIdx.x * blockDim.x + threadIdx.x;  // quad index
    const int n4 = NNODES / 4;                       // 1,250,000 (exact)
    if (i >= n4) return;
    float w = conv_w[0];
    int4   d  = reinterpret_cast<const int4*>(g_deg)[i];
    float4 xv = reinterpret_cast<const float4*>(x)[i];
    float4 p;
    p.x = xv.x * w * rsqrtf((float)(d.x + 1));
    p.y = xv.y * w * rsqrtf((float)(d.y + 1));
    p.z = xv.z * w * rsqrtf((float)(d.z + 1));
    p.w = xv.w * w * rsqrtf((float)(d.w + 1));
    reinterpret_cast<float4*>(g_p)[i]   = p;
    reinterpret_cast<float4*>(g_acc)[i] = p;
}

// ---------------------------------------------------------------------------
// 3) edge scatter: acc[col] += p[row]. One 4B gather + one 4B RED per edge.
//    (At L2-slice floor — do not disturb.)
__global__ void __launch_bounds__(256, 8)
k_edge(const long long* __restrict__ row64,
       const long long* __restrict__ col64,
       const int* __restrict__ row32,
       const int* __restrict__ col32, long long E)
{
    long long t    = (long long)blockIdx.x * blockDim.x + threadIdx.x;
    long long base = t * 4;
    if (g_is64) {
        if (base + 3 < E) {
            longlong2 r0 = *reinterpret_cast<const longlong2*>(row64 + base);
            longlong2 r1 = *reinterpret_cast<const longlong2*>(row64 + base + 2);
            longlong2 c0 = *reinterpret_cast<const longlong2*>(col64 + base);
            longlong2 c1 = *reinterpret_cast<const longlong2*>(col64 + base + 2);
            float p0 = __ldg(&g_p[(int)r0.x]);
            float p1 = __ldg(&g_p[(int)r0.y]);
            float p2 = __ldg(&g_p[(int)r1.x]);
            float p3 = __ldg(&g_p[(int)r1.y]);
            atomicAdd(&g_acc[(int)c0.x], p0);
            atomicAdd(&g_acc[(int)c0.y], p1);
            atomicAdd(&g_acc[(int)c1.x], p2);
            atomicAdd(&g_acc[(int)c1.y], p3);
        } else {
            for (long long j = base; j < E; ++j)
                atomicAdd(&g_acc[(int)col64[j]], __ldg(&g_p[(int)row64[j]]));
        }
    } else {
        if (base + 3 < E) {
            int4 r = *reinterpret_cast<const int4*>(row32 + base);
            int4 c = *reinterpret_cast<const int4*>(col32 + base);
            float p0 = __ldg(&g_p[r.x]);
            float p1 = __ldg(&g_p[r.y]);
            float p2 = __ldg(&g_p[r.z]);
            float p3 = __ldg(&g_p[r.w]);
            atomicAdd(&g_acc[c.x], p0);
            atomicAdd(&g_acc[c.y], p1);
            atomicAdd(&g_acc[c.z], p2);
            atomicAdd(&g_acc[c.w], p3);
        } else {
            for (long long j = base; j < E; ++j)
                atomicAdd(&g_acc[col32[j]], __ldg(&g_p[row32[j]]));
        }
    }
}

// ---------------------------------------------------------------------------
// 4) fused h = rsqrt(deg+1)*acc + conv_b  and per-graph FC (50 -> 2).
__global__ void k_fc(const float* __restrict__ conv_b,
                     const float* __restrict__ fc_w,   // [2,50] row-major
                     const float* __restrict__ fc_b,   // [2]
                     float* __restrict__ out)          // [NGRAPHS,2]
{
    int g = blockIdx.x * blockDim.x + threadIdx.x;
    if (g >= NGRAPHS) return;
    float b  = conv_b[0];
    float s0 = fc_b[0];
    float s1 = fc_b[1];
    int base = g * NODES_PER_GRAPH;
#pragma unroll
    for (int j = 0; j < NODES_PER_GRAPH; ++j) {
        float dis = rsqrtf((float)(g_deg[base + j] + 1));
        float h   = dis * g_acc[base + j] + b;
        s0 = fmaf(h, __ldg(&fc_w[j]), s0);
        s1 = fmaf(h, __ldg(&fc_w[NODES_PER_GRAPH + j]), s1);
    }
    out[2 * g]     = s0;
    out[2 * g + 1] = s1;
}

// ---------------------------------------------------------------------------
extern "C" void kernel_launch(void* const* d_in, const int* in_sizes, int n_in,
                              void* d_out, int out_size)
{
    // Resolve inputs BY SIZE. Sizes: x=5,000,000; edge_index=160,000,000
    // (elements, dtype int32 or int64 — detected on device);
    // conv_w=1; conv_b=1 (in appearance order); fc_w=100; fc_b=2.
    const float* x      = nullptr;
    const void*  eidx   = nullptr;
    const float* conv_w = nullptr;
    const float* conv_b = nullptr;
    const float* fc_w   = nullptr;
    const float* fc_b   = nullptr;
    long long    n_edge_elems = 0;

    for (int i = 0; i < n_in; ++i) {
        long long s = in_sizes[i];
        if (s == 160000000LL)      { eidx = d_in[i]; n_edge_elems = s; }
        else if (s == 5000000LL)   { x    = (const float*)d_in[i]; }
        else if (s == 100LL)       { fc_w = (const float*)d_in[i]; }
        else if (s == 2LL)         { fc_b = (const float*)d_in[i]; }
        else if (s == 1LL) {
            if (!conv_w) conv_w = (const float*)d_in[i];
            else         conv_b = (const float*)d_in[i];
        }
    }

    float* out = (float*)d_out;
    const long long E = n_edge_elems / 2;

    const long long* row64 = (const long long*)eidx;
    const long long* col64 = row64 + E;
    const int*       row32 = (const int*)eidx;
    const int*       col32 = row32 + E;

    const int TPB = 256;
    int prep_blocks = (NNODES / 4 + TPB - 1) / TPB;
    int edge_blocks = (int)((E + (long long)TPB * 4 - 1) / ((long long)TPB * 4));
    int fc_blocks   = (NGRAPHS + TPB - 1) / TPB;

    // Zero the degree array with a memset node (graph-capturable, no alloc).
    void* deg_ptr = nullptr;
    cudaGetSymbolAddress(&deg_ptr, g_deg);
    cudaMemsetAsync(deg_ptr, 0, (size_t)NNODES * sizeof(int), 0);

    k_detect<<<1, 1>>>((const unsigned long long*)eidx);
    k_count <<<edge_blocks, TPB>>>(col64, col32, E);
    k_prep  <<<prep_blocks, TPB>>>(x, conv_w);
    k_edge  <<<edge_blocks, TPB>>>(row64, col64, row32, col32, E);
    k_fc    <<<fc_blocks,   TPB>>>(conv_b, fc_w, fc_b, out);
}

// round 8
// speedup vs baseline: 1.5845x; 1.0022x over previous
#include <cuda_runtime.h>
#include <cstdint>

#define NNODES 5000000
#define NGRAPHS 100000
#define NODES_PER_GRAPH 50

// L2-resident scratch (60 MB total).
__device__ int   g_deg[NNODES];  // edge count (self loop added as +1 at use sites)
__device__ float g_p[NNODES];    // xw[i] * dis[i]
__device__ float g_acc[NNODES];  // running scatter sum (init = p[i] == self-loop term)

// Per-thread dtype detect: int64 indices < 2^31 have all-zero high words.
// First 16 bytes cover 2 int64s or 4 int32s; 2 random int32 indices in
// [0, 5M) are both zero with prob ~0 — but use 32 bytes (4 words) for margin.
__device__ __forceinline__ int detect_is64(const unsigned long long* e)
{
    ulonglong2 a = *reinterpret_cast<const ulonglong2*>(e);
    ulonglong2 b = *reinterpret_cast<const ulonglong2*>(e + 2);
    return ((a.x >> 32) | (a.y >> 32) | (b.x >> 32) | (b.y >> 32)) == 0ull;
}

// ---------------------------------------------------------------------------
// 1) degree count: RED.ADD to g_deg[col]. 4 edges/thread. (At L2-slice floor.)
__global__ void __launch_bounds__(256, 8)
k_count(const long long* __restrict__ col64,
        const int* __restrict__ col32,
        const unsigned long long* __restrict__ ebase, long long E)
{
    long long t    = (long long)blockIdx.x * blockDim.x + threadIdx.x;
    long long base = t * 4;
    if (detect_is64(ebase)) {
        if (base + 3 < E) {
            longlong2 a = *reinterpret_cast<const longlong2*>(col64 + base);
            longlong2 b = *reinterpret_cast<const longlong2*>(col64 + base + 2);
            atomicAdd(&g_deg[(int)a.x], 1);
            atomicAdd(&g_deg[(int)a.y], 1);
            atomicAdd(&g_deg[(int)b.x], 1);
            atomicAdd(&g_deg[(int)b.y], 1);
        } else {
            for (long long j = base; j < E; ++j)
                atomicAdd(&g_deg[(int)col64[j]], 1);
        }
    } else {
        if (base + 3 < E) {
            int4 c = *reinterpret_cast<const int4*>(col32 + base);
            atomicAdd(&g_deg[c.x], 1);
            atomicAdd(&g_deg[c.y], 1);
            atomicAdd(&g_deg[c.z], 1);
            atomicAdd(&g_deg[c.w], 1);
        } else {
            for (long long j = base; j < E; ++j)
                atomicAdd(&g_deg[col32[j]], 1);
        }
    }
}

// ---------------------------------------------------------------------------
// 2) per-node prep, 4 nodes/thread vectorized:
//    dis = rsqrt(deg+1); p = x*w*dis; acc starts at p (self-loop term).
__global__ void k_prep(const float* __restrict__ x,
                       const float* __restrict__ conv_w)
{
    int i = blockIdx.x * blockDim.x + threadIdx.x;  // quad index
    const int n4 = NNODES / 4;                       // 1,250,000 (exact)
    if (i >= n4) return;
    float w = conv_w[0];
    int4   d  = reinterpret_cast<const int4*>(g_deg)[i];
    float4 xv = reinterpret_cast<const float4*>(x)[i];
    float4 p;
    p.x = xv.x * w * rsqrtf((float)(d.x + 1));
    p.y = xv.y * w * rsqrtf((float)(d.y + 1));
    p.z = xv.z * w * rsqrtf((float)(d.z + 1));
    p.w = xv.w * w * rsqrtf((float)(d.w + 1));
    reinterpret_cast<float4*>(g_p)[i]   = p;
    reinterpret_cast<float4*>(g_acc)[i] = p;
}

// ---------------------------------------------------------------------------
// 3) edge scatter: acc[col] += p[row]. One 4B gather + one 4B RED per edge.
//    (At L2-slice floor — structure unchanged.)
__global__ void __launch_bounds__(256, 8)
k_edge(const long long* __restrict__ row64,
       const long long* __restrict__ col64,
       const int* __restrict__ row32,
       const int* __restrict__ col32,
       const unsigned long long* __restrict__ ebase, long long E)
{
    long long t    = (long long)blockIdx.x * blockDim.x + threadIdx.x;
    long long base = t * 4;
    if (detect_is64(ebase)) {
        if (base + 3 < E) {
            longlong2 r0 = *reinterpret_cast<const longlong2*>(row64 + base);
            longlong2 r1 = *reinterpret_cast<const longlong2*>(row64 + base + 2);
            longlong2 c0 = *reinterpret_cast<const longlong2*>(col64 + base);
            longlong2 c1 = *reinterpret_cast<const longlong2*>(col64 + base + 2);
            float p0 = __ldg(&g_p[(int)r0.x]);
            float p1 = __ldg(&g_p[(int)r0.y]);
            float p2 = __ldg(&g_p[(int)r1.x]);
            float p3 = __ldg(&g_p[(int)r1.y]);
            atomicAdd(&g_acc[(int)c0.x], p0);
            atomicAdd(&g_acc[(int)c0.y], p1);
            atomicAdd(&g_acc[(int)c1.x], p2);
            atomicAdd(&g_acc[(int)c1.y], p3);
        } else {
            for (long long j = base; j < E; ++j)
                atomicAdd(&g_acc[(int)col64[j]], __ldg(&g_p[(int)row64[j]]));
        }
    } else {
        if (base + 3 < E) {
            int4 r = *reinterpret_cast<const int4*>(row32 + base);
            int4 c = *reinterpret_cast<const int4*>(col32 + base);
            float p0 = __ldg(&g_p[r.x]);
            float p1 = __ldg(&g_p[r.y]);
            float p2 = __ldg(&g_p[r.z]);
            float p3 = __ldg(&g_p[r.w]);
            atomicAdd(&g_acc[c.x], p0);
            atomicAdd(&g_acc[c.y], p1);
            atomicAdd(&g_acc[c.z], p2);
            atomicAdd(&g_acc[c.w], p3);
        } else {
            for (long long j = base; j < E; ++j)
                atomicAdd(&g_acc[col32[j]], __ldg(&g_p[row32[j]]));
        }
    }
}

// ---------------------------------------------------------------------------
// 4) fused h = rsqrt(deg+1)*acc + conv_b  and per-graph FC (50 -> 2).
//    One thread per TWO graphs (100 nodes) so int4/float4 loads stay aligned.
__global__ void k_fc(const float* __restrict__ conv_b,
                     const float* __restrict__ fc_w,   // [2,50] row-major
                     const float* __restrict__ fc_b,   // [2]
                     float* __restrict__ out)          // [NGRAPHS,2]
{
    int t = blockIdx.x * blockDim.x + threadIdx.x;     // graph pair index
    const int npairs = NGRAPHS / 2;                    // 50,000
    if (t >= npairs) return;
    float b   = conv_b[0];
    float fb0 = fc_b[0];
    float fb1 = fc_b[1];
    int base = t * 2 * NODES_PER_GRAPH;                // multiple of 4

    float h[100];
#pragma unroll
    for (int q = 0; q < 25; ++q) {
        int4   d = reinterpret_cast<const int4*>(g_deg + base)[q];
        float4 a = reinterpret_cast<const float4*>(g_acc + base)[q];
        h[4 * q]     = rsqrtf((float)(d.x + 1)) * a.x + b;
        h[4 * q + 1] = rsqrtf((float)(d.y + 1)) * a.y + b;
        h[4 * q + 2] = rsqrtf((float)(d.z + 1)) * a.z + b;
        h[4 * q + 3] = rsqrtf((float)(d.w + 1)) * a.w + b;
    }
    float s00 = fb0, s01 = fb1, s10 = fb0, s11 = fb1;
#pragma unroll
    for (int j = 0; j < NODES_PER_GRAPH; ++j) {
        float w0 = __ldg(&fc_w[j]);
        float w1 = __ldg(&fc_w[NODES_PER_GRAPH + j]);
        s00 = fmaf(h[j],       w0, s00);
        s01 = fmaf(h[j],       w1, s01);
        s10 = fmaf(h[50 + j],  w0, s10);
        s11 = fmaf(h[50 + j],  w1, s11);
    }
    int g = t * 2;
    reinterpret_cast<float4*>(out)[t] = make_float4(s00, s01, s10, s11);
    (void)g;
}

// ---------------------------------------------------------------------------
extern "C" void kernel_launch(void* const* d_in, const int* in_sizes, int n_in,
                              void* d_out, int out_size)
{
    // Resolve inputs BY SIZE. Sizes: x=5,000,000; edge_index=160,000,000
    // (elements, dtype int32 or int64 — detected on device);
    // conv_w=1; conv_b=1 (in appearance order); fc_w=100; fc_b=2.
    const float* x      = nullptr;
    const void*  eidx   = nullptr;
    const float* conv_w = nullptr;
    const float* conv_b = nullptr;
    const float* fc_w   = nullptr;
    const float* fc_b   = nullptr;
    long long    n_edge_elems = 0;

    for (int i = 0; i < n_in; ++i) {
        long long s = in_sizes[i];
        if (s == 160000000LL)      { eidx = d_in[i]; n_edge_elems = s; }
        else if (s == 5000000LL)   { x    = (const float*)d_in[i]; }
        else if (s == 100LL)       { fc_w = (const float*)d_in[i]; }
        else if (s == 2LL)         { fc_b = (const float*)d_in[i]; }
        else if (s == 1LL) {
            if (!conv_w) conv_w = (const float*)d_in[i];
            else         conv_b = (const float*)d_in[i];
        }
    }

    float* out = (float*)d_out;
    const long long E = n_edge_elems / 2;

    const long long* row64 = (const long long*)eidx;
    const long long* col64 = row64 + E;
    const int*       row32 = (const int*)eidx;
    const int*       col32 = row32 + E;
    const unsigned long long* ebase = (const unsigned long long*)eidx;

    const int TPB = 256;
    int prep_blocks = (NNODES / 4 + TPB - 1) / TPB;
    int edge_blocks = (int)((E + (long long)TPB * 4 - 1) / ((long long)TPB * 4));
    int fc_blocks   = (NGRAPHS / 2 + TPB - 1) / TPB;

    // Zero the degree array with a memset node (graph-capturable, no alloc).
    void* deg_ptr = nullptr;
    cudaGetSymbolAddress(&deg_ptr, g_deg);
    cudaMemsetAsync(deg_ptr, 0, (size_t)NNODES * sizeof(int), 0);

    k_count<<<edge_blocks, TPB>>>(col64, col32, ebase, E);
    k_prep <<<prep_blocks, TPB>>>(x, conv_w);
    k_edge <<<edge_blocks, TPB>>>(row64, col64, row32, col32, ebase, E);
    k_fc   <<<fc_blocks,   TPB>>>(conv_b, fc_w, fc_b, out);
}